// round 8
// baseline (speedup 1.0000x reference)
#include <cuda_runtime.h>

#define T_STEPS 4096
#define NCTA    128
#define NTHR    512

typedef unsigned long long ull;

// ---------------- global scratch (static; no allocs) ----------------
// h layout: [m][b] floats (m = hidden unit 0..255, b = batch 0..63)
__device__ __align__(256) float g_h0[2][256][64];     // double-buffered h0 broadcast
__device__ __align__(256) float g_h1[4098][256][64];  // h1 history: slot t+2 = h1(t)
__device__ __align__(256) float g_yT[4099][64];       // yT[t+3][b] = y[b][t]; rows 0..2 pad
__device__ unsigned g_cnt;    // zero-init; returns to 0 (reset each barrier)
__device__ unsigned g_sense;  // zero-init; returns to 0 (even total round count: 4098)

// ---------------- helpers ----------------
__device__ __forceinline__ ull ffma2(ull h, ull w, ull a) {
    ull d;
    asm("fma.rn.f32x2 %0, %1, %2, %3;" : "=l"(d) : "l"(h), "l"(w), "l"(a));
    return d;
}
__device__ __forceinline__ ull pack2(float f) {
    unsigned u = __float_as_uint(f);
    return ((ull)u << 32) | (ull)u;
}
__device__ __forceinline__ float sigf(float x)   { return 1.0f / (1.0f + __expf(-x)); }
__device__ __forceinline__ float tanh_f(float x) { return 2.0f * sigf(2.0f * x) - 1.0f; }

__device__ __forceinline__ ull ldcg1(const float* p) {
    ull v;
    asm volatile("ld.global.cg.u64 %0, [%1];" : "=l"(v) : "l"(p));
    return v;
}
__device__ __forceinline__ unsigned atom_add_acqrel(unsigned* p, unsigned v) {
    unsigned old;
    asm volatile("atom.acq_rel.gpu.global.add.u32 %0, [%1], %2;"
                 : "=r"(old) : "l"(p), "r"(v) : "memory");
    return old;
}
__device__ __forceinline__ unsigned ld_acquire(const unsigned* p) {
    unsigned v;
    asm volatile("ld.acquire.gpu.global.u32 %0, [%1];" : "=r"(v) : "l"(p) : "memory");
    return v;
}
__device__ __forceinline__ void st_release(unsigned* p, unsigned v) {
    asm volatile("st.release.gpu.global.u32 [%0], %1;" :: "l"(p), "r"(v) : "memory");
}
__device__ __forceinline__ void st_relaxed(unsigned* p, unsigned v) {
    asm volatile("st.relaxed.gpu.global.u32 [%0], %1;" :: "l"(p), "r"(v) : "memory");
}

// self-resetting sense-reversing grid barrier; ALL threads poll (1 req/warp, uniform addr)
__device__ __forceinline__ void grid_barrier(int tid, unsigned& ls) {
    __syncthreads();
    ls ^= 1u;
    if (tid == 0) {
        unsigned old = atom_add_acqrel(&g_cnt, 1u);
        if (old == NCTA - 1u) {
            st_relaxed(&g_cnt, 0u);
            st_release(&g_sense, ls);
        }
    }
    while (ld_acquire(&g_sense) != ls) { }
}

// ---------------- the whole problem in one kernel ----------------
// smem layout (bytes):
//   W0v2 ulonglong2[1024] @ 0      16384  W_hh0 dup-pairs [16q][8r][8 ull2]
//   W1v2 ulonglong2[1024] @ 16384  16384  W_ih1
//   WHv2 ulonglong2[1024] @ 32768  16384  W_hh1
//   P0u  ull[4096]        @ 49152  32768  layer0 partials [16q][8r][32 bp]
//   P1u  ull[4096]        @ 81920  32768
//   floats @ 114688: wih0[32] b0s[8] b1s[8] c0s[128] c1s[128] yw[256] wout[512] bo2[2]
#define SMEM_BYTES (114688 + 4288)

__global__ void __launch_bounds__(NTHR, 1) lstm_all(
    const float* __restrict__ y,
    const float* __restrict__ Wih0, const float* __restrict__ Whh0,
    const float* __restrict__ bih0, const float* __restrict__ bhh0,
    const float* __restrict__ Wih1, const float* __restrict__ Whh1,
    const float* __restrict__ bih1, const float* __restrict__ bhh1,
    const float* __restrict__ Wout, const float* __restrict__ bout,
    float* __restrict__ out)
{
    extern __shared__ char smraw[];
    ulonglong2* W0v2 = (ulonglong2*)smraw;
    ulonglong2* W1v2 = (ulonglong2*)(smraw + 16384);
    ulonglong2* WHv2 = (ulonglong2*)(smraw + 32768);
    ull*        P0u  = (ull*)(smraw + 49152);
    ull*        P1u  = (ull*)(smraw + 81920);
    float* fs   = (float*)(smraw + 114688);
    float* wih0 = fs;            // [8][4]
    float* b0s  = fs + 32;       // [8]
    float* b1s  = fs + 40;       // [8]
    float* c0s  = fs + 48;       // [2][64]
    float* c1s  = fs + 176;      // [2][64]
    float* yw   = fs + 304;      // [4][64]
    float* wout = fs + 560;      // [2][256]
    float* bo2  = fs + 1072;     // [2]

    const int tid = threadIdx.x;
    const int bid = blockIdx.x;
    const int j0  = bid * 2;                 // CTA owns hidden units j0, j0+1
    unsigned ls = 0;

    // ======== init: global state ========
    {
        int gi = bid * NTHR + tid;           // 0..65535
        if (gi < 32768) {                    // zero h0 (both bufs) + h1 slots 0,1
            ((float*)g_h0)[gi] = 0.0f;
            ((float*)g_h1)[gi] = 0.0f;
        }
        for (int i = gi; i < 4099 * 64; i += NCTA * NTHR) {
            int row = i >> 6, b = i & 63;
            g_yT[row][b] = (row < 3) ? -100.0f : y[b * T_STEPS + (row - 3)];
        }
    }

    // ======== init: smem weights, dup-pairs ========
    // flat ull index u = q*128 + r*16 + k ; global m = q*16 + k
    {
        ull* W0u = (ull*)W0v2; ull* W1u = (ull*)W1v2; ull* WHu = (ull*)WHv2;
        for (int u = tid; u < 2048; u += NTHR) {
            int k = u & 15;
            int r = (u >> 4) & 7;
            int q = u >> 7;
            int m   = q * 16 + k;
            int row = (r >> 1) * 256 + j0 + (r & 1);
            W0u[u] = pack2(Whh0[row * 256 + m]);
            W1u[u] = pack2(Wih1[row * 256 + m]);
            WHu[u] = pack2(Whh1[row * 256 + m]);
        }
        if (tid < 8) {
            int row = (tid >> 1) * 256 + j0 + (tid & 1);
            b0s[tid] = bih0[row] + bhh0[row];
            b1s[tid] = bih1[row] + bhh1[row];
            for (int k = 0; k < 4; k++) wih0[tid * 4 + k] = Wih0[row * 4 + k];
        }
        if (tid < 128) { c0s[tid] = 0.0f; c1s[tid] = 0.0f; }
        if (tid < 512) wout[tid] = Wout[tid];
        if (tid < 2) bo2[tid] = bout[tid];
    }
    grid_barrier(tid, ls);   // round 1

    // ======== persistent 2-layer LSTM ========
    const int g  = tid & 31;         // batch pair: batches 2g, 2g+1
    const int q  = tid >> 5;         // m-chunk (16 chunks of 16 m); warp-uniform
    const ulonglong2* W0q = W0v2 + q * 64;   // + r*8 + (c*4+i)
    const ulonglong2* W1q = W1v2 + q * 64;
    const ulonglong2* WHq = WHv2 + q * 64;
    const int hoff = q * 16 * 64 + 2 * g;

    for (int p = 0; p <= T_STEPS; p++) {
        const float* H0 = &g_h0[p & 1][0][0] + hoff;   // h0(p-1) slice
        const float* H1 = &g_h1[p][0][0]     + hoff;   // h1(p-2) slice
        if (tid < 256 && p < T_STEPS) yw[tid] = g_yT[p + (tid >> 6)][tid & 63];

        ull a0[8], a1[8];
        #pragma unroll
        for (int r = 0; r < 8; r++) { a0[r] = 0ull; a1[r] = 0ull; }

        ull hb[2][8];
        #pragma unroll
        for (int k = 0; k < 8; k++) hb[0][k] = ldcg1(H0 + k * 64);

        #pragma unroll
        for (int c = 0; c < 4; c++) {
            const int cb = c & 1;
            if (c < 3) {   // prefetch next 8-m chunk
                const float* nb = (c == 0) ? (H0 + 8 * 64) : (H1 + (c - 1) * 8 * 64);
                #pragma unroll
                for (int k = 0; k < 8; k++) hb[cb ^ 1][k] = ldcg1(nb + k * 64);
            }
            if (c < 2) {   // h0 chunk: feeds layer0 (W0) and layer1-ih (W1)
                #pragma unroll
                for (int i = 0; i < 4; i++) {
                    const ull hA = hb[cb][2 * i], hB = hb[cb][2 * i + 1];
                    #pragma unroll
                    for (int r = 0; r < 8; r++) {
                        ulonglong2 w0 = W0q[r * 8 + c * 4 + i];
                        a0[r] = ffma2(hA, w0.x, a0[r]);
                        a0[r] = ffma2(hB, w0.y, a0[r]);
                        ulonglong2 w1 = W1q[r * 8 + c * 4 + i];
                        a1[r] = ffma2(hA, w1.x, a1[r]);
                        a1[r] = ffma2(hB, w1.y, a1[r]);
                    }
                }
            } else {       // h1 chunk: feeds layer1-hh (WH)
                #pragma unroll
                for (int i = 0; i < 4; i++) {
                    const ull hA = hb[cb][2 * i], hB = hb[cb][2 * i + 1];
                    #pragma unroll
                    for (int r = 0; r < 8; r++) {
                        ulonglong2 wh = WHq[r * 8 + (c - 2) * 4 + i];
                        a1[r] = ffma2(hA, wh.x, a1[r]);
                        a1[r] = ffma2(hB, wh.y, a1[r]);
                    }
                }
            }
        }
        #pragma unroll
        for (int r = 0; r < 8; r++) {
            P0u[(q * 8 + r) * 32 + g] = a0[r];
            P1u[(q * 8 + r) * 32 + g] = a1[r];
        }
        __syncthreads();

        // ---- reduce 16 partials, cell update, publish h (256 threads) ----
        if (tid < 256) {
            const int lb    = tid & 63;
            const int lj    = (tid >> 6) & 1;
            const int half2 = tid >> 7;     // 0: layer0 cell, 1: layer1 cell
            const bool act  = half2 ? (p > 0) : (p < T_STEPS);
            if (act) {
                const float* P = (const float*)(half2 ? P1u : P0u);
                float gg[4];
                #pragma unroll
                for (int gt = 0; gt < 4; gt++) {
                    int r = gt * 2 + lj;
                    float s = 0.0f;
                    #pragma unroll
                    for (int qq = 0; qq < 16; qq++)
                        s += P[(qq * 8 + r) * 64 + lb];
                    gg[gt] = s;
                }
                if (half2 == 0) {
                    #pragma unroll
                    for (int gt = 0; gt < 4; gt++) {
                        int r = gt * 2 + lj;
                        float s = gg[gt] + b0s[r];
                        #pragma unroll
                        for (int k = 0; k < 4; k++)
                            s = fmaf(yw[k * 64 + lb], wih0[r * 4 + k], s);
                        gg[gt] = s;
                    }
                } else {
                    #pragma unroll
                    for (int gt = 0; gt < 4; gt++)
                        gg[gt] += b1s[gt * 2 + lj];
                }
                float* cs = half2 ? c1s : c0s;
                float c = cs[lj * 64 + lb];
                c = sigf(gg[1]) * c + sigf(gg[0]) * tanh_f(gg[2]);
                cs[lj * 64 + lb] = c;
                float h = sigf(gg[3]) * tanh_f(c);
                int j = j0 + lj;
                if (half2 == 0) g_h0[(p + 1) & 1][j][lb] = h;   // h0(p)
                else            g_h1[p + 1][j][lb]       = h;   // h1(p-1)
            }
        }
        grid_barrier(tid, ls);   // rounds 2..4098 (even total -> sense returns to 0)
    }

    // ======== output projection: out[b][t][k] = h1(t).Wout[k] + bout[k] ========
    {
        const int b  = tid & 63;
        const int tt = tid >> 6;    // 0..7
        #pragma unroll
        for (int u = 0; u < 4; u++) {
            int t = bid * 32 + tt * 4 + u;
            const float* h = &g_h1[t + 2][0][0];
            float s0 = bo2[0], s1 = bo2[1];
            #pragma unroll 8
            for (int m = 0; m < 256; m++) {
                float v = h[m * 64 + b];
                s0 = fmaf(v, wout[m],       s0);
                s1 = fmaf(v, wout[256 + m], s1);
            }
            out[b * (T_STEPS * 2) + t * 2 + 0] = s0;
            out[b * (T_STEPS * 2) + t * 2 + 1] = s1;
        }
    }
}

// ---------------- launcher: ONE kernel ----------------
extern "C" void kernel_launch(void* const* d_in, const int* in_sizes, int n_in,
                              void* d_out, int out_size)
{
    (void)in_sizes; (void)n_in; (void)out_size;
    cudaFuncSetAttribute(lstm_all, cudaFuncAttributeMaxDynamicSharedMemorySize, SMEM_BYTES);
    lstm_all<<<NCTA, NTHR, SMEM_BYTES>>>(
        (const float*)d_in[0],
        (const float*)d_in[1], (const float*)d_in[2],
        (const float*)d_in[3], (const float*)d_in[4],
        (const float*)d_in[5], (const float*)d_in[6],
        (const float*)d_in[7], (const float*)d_in[8],
        (const float*)d_in[9], (const float*)d_in[10],
        (float*)d_out);
}

// round 9
// speedup vs baseline: 1.1563x; 1.1563x over previous
#include <cuda_runtime.h>

#define T_STEPS 4096
#define NCTA    128
#define NTHR    512

typedef unsigned long long ull;

// ---------------- global scratch (static; no allocs) ----------------
// h layout: [m][b] floats (m = hidden unit 0..255, b = batch 0..63)
__device__ __align__(256) float g_h0[2][256][64];     // double-buffered h0 broadcast
__device__ __align__(256) float g_h1[4098][256][64];  // h1 history: slot t+2 = h1(t)
__device__ __align__(256) float g_yT[4099][64];       // yT[t+3][b] = y[b][t]; rows 0..2 pad
__device__ unsigned g_cnt;    // zero-init; reset to 0 each barrier
__device__ unsigned g_sense;  // zero-init; even total round count (4098) -> returns to 0

// ---------------- helpers ----------------
__device__ __forceinline__ ull ffma2(ull h, ull w, ull a) {
    ull d;
    asm("fma.rn.f32x2 %0, %1, %2, %3;" : "=l"(d) : "l"(h), "l"(w), "l"(a));
    return d;
}
__device__ __forceinline__ ull pack2(float f) {
    unsigned u = __float_as_uint(f);
    return ((ull)u << 32) | (ull)u;
}
__device__ __forceinline__ float sigf(float x)   { return 1.0f / (1.0f + __expf(-x)); }
__device__ __forceinline__ float tanh_f(float x) { return 2.0f * sigf(2.0f * x) - 1.0f; }

__device__ __forceinline__ ull ldcg1(const float* p) {
    ull v;
    asm volatile("ld.global.cg.u64 %0, [%1];" : "=l"(v) : "l"(p));
    return v;
}
__device__ __forceinline__ unsigned atom_add_acqrel(unsigned* p, unsigned v) {
    unsigned old;
    asm volatile("atom.acq_rel.gpu.global.add.u32 %0, [%1], %2;"
                 : "=r"(old) : "l"(p), "r"(v) : "memory");
    return old;
}
__device__ __forceinline__ unsigned ld_acquire(const unsigned* p) {
    unsigned v;
    asm volatile("ld.acquire.gpu.global.u32 %0, [%1];" : "=r"(v) : "l"(p) : "memory");
    return v;
}
__device__ __forceinline__ void st_release(unsigned* p, unsigned v) {
    asm volatile("st.release.gpu.global.u32 [%0], %1;" :: "l"(p), "r"(v) : "memory");
}
__device__ __forceinline__ void st_relaxed(unsigned* p, unsigned v) {
    asm volatile("st.relaxed.gpu.global.u32 [%0], %1;" :: "l"(p), "r"(v) : "memory");
}

// self-resetting sense-reversing grid barrier; ONLY tid 0 polls (128 pollers chip-wide),
// __syncthreads broadcasts the release to the other warps.
__device__ __forceinline__ void grid_barrier(int tid, unsigned& ls) {
    __syncthreads();
    ls ^= 1u;
    if (tid == 0) {
        unsigned old = atom_add_acqrel(&g_cnt, 1u);
        if (old == NCTA - 1u) {
            st_relaxed(&g_cnt, 0u);
            st_release(&g_sense, ls);
        } else {
            while (ld_acquire(&g_sense) != ls) { }
        }
    }
    __syncthreads();
}

// ---------------- the whole problem in one kernel ----------------
// smem layout (bytes):
//   W0v2 ulonglong2[1024] @ 0      16384  W_hh0 dup-pairs [16q][8r][8 ull2]
//   W1v2 ulonglong2[1024] @ 16384  16384  W_ih1
//   WHv2 ulonglong2[1024] @ 32768  16384  W_hh1
//   P0u  ull[4096]        @ 49152  32768  layer0 partials [16q][8r][32 bp]
//   P1u  ull[4096]        @ 81920  32768
//   floats @ 114688: wih0[32] b0s[8] b1s[8] c0s[128] c1s[128] yw[256] wout[512] bo2[2]
#define SMEM_BYTES (114688 + 4288)

__global__ void __launch_bounds__(NTHR, 1) lstm_all(
    const float* __restrict__ y,
    const float* __restrict__ Wih0, const float* __restrict__ Whh0,
    const float* __restrict__ bih0, const float* __restrict__ bhh0,
    const float* __restrict__ Wih1, const float* __restrict__ Whh1,
    const float* __restrict__ bih1, const float* __restrict__ bhh1,
    const float* __restrict__ Wout, const float* __restrict__ bout,
    float* __restrict__ out)
{
    extern __shared__ char smraw[];
    ulonglong2* W0v2 = (ulonglong2*)smraw;
    ulonglong2* W1v2 = (ulonglong2*)(smraw + 16384);
    ulonglong2* WHv2 = (ulonglong2*)(smraw + 32768);
    ull*        P0u  = (ull*)(smraw + 49152);
    ull*        P1u  = (ull*)(smraw + 81920);
    float* fs   = (float*)(smraw + 114688);
    float* wih0 = fs;            // [8][4]
    float* b0s  = fs + 32;       // [8]
    float* b1s  = fs + 40;       // [8]
    float* c0s  = fs + 48;       // [2][64]
    float* c1s  = fs + 176;      // [2][64]
    float* yw   = fs + 304;      // [4][64]
    float* wout = fs + 560;      // [2][256]
    float* bo2  = fs + 1072;     // [2]

    const int tid = threadIdx.x;
    const int bid = blockIdx.x;
    const int j0  = bid * 2;                 // CTA owns hidden units j0, j0+1
    unsigned ls = 0;

    // ======== init: global state ========
    {
        int gi = bid * NTHR + tid;           // 0..65535
        if (gi < 32768) {                    // zero h0 (both bufs) + h1 slots 0,1
            ((float*)g_h0)[gi] = 0.0f;
            ((float*)g_h1)[gi] = 0.0f;
        }
        for (int i = gi; i < 4099 * 64; i += NCTA * NTHR) {
            int row = i >> 6, b = i & 63;
            g_yT[row][b] = (row < 3) ? -100.0f : y[b * T_STEPS + (row - 3)];
        }
    }

    // ======== init: smem weights, dup-pairs ========
    // flat ull index u = q*128 + r*16 + k ; global m = q*16 + k
    {
        ull* W0u = (ull*)W0v2; ull* W1u = (ull*)W1v2; ull* WHu = (ull*)WHv2;
        for (int u = tid; u < 2048; u += NTHR) {
            int k = u & 15;
            int r = (u >> 4) & 7;
            int q = u >> 7;
            int m   = q * 16 + k;
            int row = (r >> 1) * 256 + j0 + (r & 1);
            W0u[u] = pack2(Whh0[row * 256 + m]);
            W1u[u] = pack2(Wih1[row * 256 + m]);
            WHu[u] = pack2(Whh1[row * 256 + m]);
        }
        if (tid < 8) {
            int row = (tid >> 1) * 256 + j0 + (tid & 1);
            b0s[tid] = bih0[row] + bhh0[row];
            b1s[tid] = bih1[row] + bhh1[row];
            for (int k = 0; k < 4; k++) wih0[tid * 4 + k] = Wih0[row * 4 + k];
        }
        if (tid < 128) { c0s[tid] = 0.0f; c1s[tid] = 0.0f; }
        if (tid < 512) wout[tid] = Wout[tid];
        if (tid < 2) bo2[tid] = bout[tid];
    }
    grid_barrier(tid, ls);   // round 1

    // ======== persistent 2-layer LSTM ========
    const int g  = tid & 31;         // batch pair: batches 2g, 2g+1
    const int q  = tid >> 5;         // m-chunk (16 chunks of 16 m); warp-uniform
    const ulonglong2* W0q = W0v2 + q * 64;   // + r*8 + (c*4+i)
    const ulonglong2* W1q = W1v2 + q * 64;
    const ulonglong2* WHq = WHv2 + q * 64;
    const int hoff = q * 16 * 64 + 2 * g;

    for (int p = 0; p <= T_STEPS; p++) {
        const float* H0 = &g_h0[p & 1][0][0] + hoff;   // h0(p-1) slice
        const float* H1 = &g_h1[p][0][0]     + hoff;   // h1(p-2) slice
        if (tid < 256 && p < T_STEPS) yw[tid] = g_yT[p + (tid >> 6)][tid & 63];

        ull a0[8], a1[8];
        #pragma unroll
        for (int r = 0; r < 8; r++) { a0[r] = 0ull; a1[r] = 0ull; }

        ull hb[2][8];
        #pragma unroll
        for (int k = 0; k < 8; k++) hb[0][k] = ldcg1(H0 + k * 64);

        #pragma unroll
        for (int c = 0; c < 4; c++) {
            const int cb = c & 1;
            if (c < 3) {   // prefetch next 8-m chunk
                const float* nb = (c == 0) ? (H0 + 8 * 64) : (H1 + (c - 1) * 8 * 64);
                #pragma unroll
                for (int k = 0; k < 8; k++) hb[cb ^ 1][k] = ldcg1(nb + k * 64);
            }
            if (c < 2) {   // h0 chunk: feeds layer0 (W0) and layer1-ih (W1)
                #pragma unroll
                for (int i = 0; i < 4; i++) {
                    const ull hA = hb[cb][2 * i], hB = hb[cb][2 * i + 1];
                    #pragma unroll
                    for (int r = 0; r < 8; r++) {
                        ulonglong2 w0 = W0q[r * 8 + c * 4 + i];
                        a0[r] = ffma2(hA, w0.x, a0[r]);
                        a0[r] = ffma2(hB, w0.y, a0[r]);
                        ulonglong2 w1 = W1q[r * 8 + c * 4 + i];
                        a1[r] = ffma2(hA, w1.x, a1[r]);
                        a1[r] = ffma2(hB, w1.y, a1[r]);
                    }
                }
            } else {       // h1 chunk: feeds layer1-hh (WH)
                #pragma unroll
                for (int i = 0; i < 4; i++) {
                    const ull hA = hb[cb][2 * i], hB = hb[cb][2 * i + 1];
                    #pragma unroll
                    for (int r = 0; r < 8; r++) {
                        ulonglong2 wh = WHq[r * 8 + (c - 2) * 4 + i];
                        a1[r] = ffma2(hA, wh.x, a1[r]);
                        a1[r] = ffma2(hB, wh.y, a1[r]);
                    }
                }
            }
        }
        #pragma unroll
        for (int r = 0; r < 8; r++) {
            P0u[(q * 8 + r) * 32 + g] = a0[r];
            P1u[(q * 8 + r) * 32 + g] = a1[r];
        }
        __syncthreads();

        // ---- reduce 16 partials, cell update, publish h (256 threads) ----
        if (tid < 256) {
            const int lb    = tid & 63;
            const int lj    = (tid >> 6) & 1;
            const int half2 = tid >> 7;     // 0: layer0 cell, 1: layer1 cell
            const bool act  = half2 ? (p > 0) : (p < T_STEPS);
            if (act) {
                const float* P = (const float*)(half2 ? P1u : P0u);
                float gg[4];
                #pragma unroll
                for (int gt = 0; gt < 4; gt++) {
                    int r = gt * 2 + lj;
                    float s = 0.0f;
                    #pragma unroll
                    for (int qq = 0; qq < 16; qq++)
                        s += P[(qq * 8 + r) * 64 + lb];
                    gg[gt] = s;
                }
                if (half2 == 0) {
                    #pragma unroll
                    for (int gt = 0; gt < 4; gt++) {
                        int r = gt * 2 + lj;
                        float s = gg[gt] + b0s[r];
                        #pragma unroll
                        for (int k = 0; k < 4; k++)
                            s = fmaf(yw[k * 64 + lb], wih0[r * 4 + k], s);
                        gg[gt] = s;
                    }
                } else {
                    #pragma unroll
                    for (int gt = 0; gt < 4; gt++)
                        gg[gt] += b1s[gt * 2 + lj];
                }
                float* cs = half2 ? c1s : c0s;
                float c = cs[lj * 64 + lb];
                c = sigf(gg[1]) * c + sigf(gg[0]) * tanh_f(gg[2]);
                cs[lj * 64 + lb] = c;
                float h = sigf(gg[3]) * tanh_f(c);
                int j = j0 + lj;
                if (half2 == 0) g_h0[(p + 1) & 1][j][lb] = h;   // h0(p)
                else            g_h1[p + 1][j][lb]       = h;   // h1(p-1)
            }
        }
        grid_barrier(tid, ls);   // rounds 2..4098 (even total -> sense returns to 0)
    }

    // ======== output projection: out[b][t][k] = h1(t).Wout[k] + bout[k] ========
    {
        const int b  = tid & 63;
        const int tt = tid >> 6;    // 0..7
        #pragma unroll
        for (int u = 0; u < 4; u++) {
            int t = bid * 32 + tt * 4 + u;
            const float* h = &g_h1[t + 2][0][0];
            float s0 = bo2[0], s1 = bo2[1];
            #pragma unroll 8
            for (int m = 0; m < 256; m++) {
                float v = h[m * 64 + b];
                s0 = fmaf(v, wout[m],       s0);
                s1 = fmaf(v, wout[256 + m], s1);
            }
            out[b * (T_STEPS * 2) + t * 2 + 0] = s0;
            out[b * (T_STEPS * 2) + t * 2 + 1] = s1;
        }
    }
}

// ---------------- launcher: ONE kernel ----------------
extern "C" void kernel_launch(void* const* d_in, const int* in_sizes, int n_in,
                              void* d_out, int out_size)
{
    (void)in_sizes; (void)n_in; (void)out_size;
    cudaFuncSetAttribute(lstm_all, cudaFuncAttributeMaxDynamicSharedMemorySize, SMEM_BYTES);
    lstm_all<<<NCTA, NTHR, SMEM_BYTES>>>(
        (const float*)d_in[0],
        (const float*)d_in[1], (const float*)d_in[2],
        (const float*)d_in[3], (const float*)d_in[4],
        (const float*)d_in[5], (const float*)d_in[6],
        (const float*)d_in[7], (const float*)d_in[8],
        (const float*)d_in[9], (const float*)d_in[10],
        (float*)d_out);
}

// round 10
// speedup vs baseline: 1.3810x; 1.1943x over previous
#include <cuda_runtime.h>

#define T_STEPS 4096
#define NCTA    128
#define NTHR    256

typedef unsigned long long ull;

// ---------------- global scratch (static; no allocs) ----------------
// h layout: [m][b] floats (m = hidden unit 0..255, b = batch 0..63)
__device__ __align__(256) float g_h0[3][256][64];     // triple-buffered h0: h0(s) at slot s%3
__device__ __align__(256) float g_h1[4100][256][64];  // h1(s) at slot s+3; slots 0..2 zero
__device__ __align__(256) float g_yT[4099][64];       // yT[t+3][b] = y[b][t]; rows 0..2 pad
__device__ unsigned g_cnt;    // zero-init; reset to 0 each barrier
__device__ unsigned g_sense;  // zero-init; even total round count (4100) -> returns to 0

// ---------------- helpers ----------------
__device__ __forceinline__ ull ffma2(ull h, ull w, ull a) {
    ull d;
    asm("fma.rn.f32x2 %0, %1, %2, %3;" : "=l"(d) : "l"(h), "l"(w), "l"(a));
    return d;
}
__device__ __forceinline__ ull pack2(float f) {
    unsigned u = __float_as_uint(f);
    return ((ull)u << 32) | (ull)u;
}
__device__ __forceinline__ float sigf(float x)   { return 1.0f / (1.0f + __expf(-x)); }
__device__ __forceinline__ float tanh_f(float x) { return 2.0f * sigf(2.0f * x) - 1.0f; }

__device__ __forceinline__ ulonglong2 ldcg2(const float* p) {
    ulonglong2 v;
    asm volatile("ld.global.cg.v2.u64 {%0,%1}, [%2];" : "=l"(v.x), "=l"(v.y) : "l"(p));
    return v;
}
__device__ __forceinline__ unsigned atom_add_acqrel(unsigned* p, unsigned v) {
    unsigned old;
    asm volatile("atom.acq_rel.gpu.global.add.u32 %0, [%1], %2;"
                 : "=r"(old) : "l"(p), "r"(v) : "memory");
    return old;
}
__device__ __forceinline__ unsigned ld_acquire(const unsigned* p) {
    unsigned v;
    asm volatile("ld.acquire.gpu.global.u32 %0, [%1];" : "=r"(v) : "l"(p) : "memory");
    return v;
}
__device__ __forceinline__ void st_release(unsigned* p, unsigned v) {
    asm volatile("st.release.gpu.global.u32 [%0], %1;" :: "l"(p), "r"(v) : "memory");
}
__device__ __forceinline__ void st_relaxed(unsigned* p, unsigned v) {
    asm volatile("st.relaxed.gpu.global.u32 [%0], %1;" :: "l"(p), "r"(v) : "memory");
}

// self-resetting sense-reversing grid barrier; only tid 0 polls.
__device__ __forceinline__ void grid_barrier(int tid, unsigned& ls) {
    __syncthreads();
    ls ^= 1u;
    if (tid == 0) {
        unsigned old = atom_add_acqrel(&g_cnt, 1u);
        if (old == NCTA - 1u) {
            st_relaxed(&g_cnt, 0u);
            st_release(&g_sense, ls);
        } else {
            while (ld_acquire(&g_sense) != ls) { }
        }
    }
    __syncthreads();
}

// ---------------- smem layout (bytes) ----------------
//   W0u ull[2048] @ 0      16384  W_hh0 dup-pairs, half-warp interleaved
//   W1u ull[2048] @ 16384  16384  W_ih1
//   WHu ull[2048] @ 32768  16384  W_hh1
//   P0  ull2[2048]@ 49152  32768  layer0 partials [16q][8r][16g]{lo,hi}
//   P1  ull2[2048]@ 81920  32768
//   floats @ 114688: wih0[32] b0s[8] b1s[8] c0s[128] c1s[128] yw[256]
//                    wout[512] bo2[2]
#define SMEM_BYTES (114688 + 4296)

// FMA micro-block: 8-m group HREG[8] (one ull2 per m) vs weight region at ull2
// index (wb + r*16 + (IB + i)*2), accumulating into ALO/AHI[8].
#define FMA8(WV, IB, HREG, ALO, AHI)                                   \
    _Pragma("unroll")                                                   \
    for (int i = 0; i < 4; i++) {                                       \
        const ulonglong2 hA = HREG[2*i], hB = HREG[2*i+1];              \
        _Pragma("unroll")                                               \
        for (int r = 0; r < 8; r++) {                                   \
            ulonglong2 wv = WV[wb + r * 16 + (IB + i) * 2];             \
            ALO[r] = ffma2(hA.x, wv.x, ALO[r]);                         \
            AHI[r] = ffma2(hA.y, wv.x, AHI[r]);                         \
            ALO[r] = ffma2(hB.x, wv.y, ALO[r]);                         \
            AHI[r] = ffma2(hB.y, wv.y, AHI[r]);                         \
        }                                                               \
    }

__global__ void __launch_bounds__(NTHR, 1) lstm_all(
    const float* __restrict__ y,
    const float* __restrict__ Wih0, const float* __restrict__ Whh0,
    const float* __restrict__ bih0, const float* __restrict__ bhh0,
    const float* __restrict__ Wih1, const float* __restrict__ Whh1,
    const float* __restrict__ bih1, const float* __restrict__ bhh1,
    const float* __restrict__ Wout, const float* __restrict__ bout,
    float* __restrict__ out)
{
    extern __shared__ char smraw[];
    ull*        W0u = (ull*)smraw;
    ull*        W1u = (ull*)(smraw + 16384);
    ull*        WHu = (ull*)(smraw + 32768);
    ulonglong2* P0v = (ulonglong2*)(smraw + 49152);
    ulonglong2* P1v = (ulonglong2*)(smraw + 81920);
    const ulonglong2* W0v = (const ulonglong2*)W0u;
    const ulonglong2* W1v = (const ulonglong2*)W1u;
    const ulonglong2* WHv = (const ulonglong2*)WHu;
    float* fs   = (float*)(smraw + 114688);
    float* wih0 = fs;            // [8][4]
    float* b0s  = fs + 32;       // [8]
    float* b1s  = fs + 40;       // [8]
    float* c0s  = fs + 48;       // [2][64]
    float* c1s  = fs + 176;      // [2][64]
    float* yw   = fs + 304;      // [4][64]
    float* wout = fs + 560;      // [2][256]
    float* bo2  = fs + 1072;     // [2]

    const int tid = threadIdx.x;
    const int bid = blockIdx.x;
    const int j0  = bid * 2;                 // CTA owns hidden units j0, j0+1
    unsigned ls = 0;

    // ======== init: global state ========
    {
        int gi = bid * NTHR + tid;           // 0..32767
        for (int i = gi; i < 49152; i += NCTA * NTHR) {
            ((float*)g_h0)[i] = 0.0f;        // all 3 h0 slots
            ((float*)g_h1)[i] = 0.0f;        // h1 slots 0..2
        }
        for (int i = gi; i < 4099 * 64; i += NCTA * NTHR) {
            int row = i >> 6, b = i & 63;
            g_yT[row][b] = (row < 3) ? -100.0f : y[b * T_STEPS + (row - 3)];
        }
    }

    // ======== init: smem weights (dup-pairs, half-warp interleaved) ========
    // flat ull index u = w*256 + r*32 + i*4 + hf*2 + j ; m = (w*2+hf)*16 + 2i + j
    {
        for (int u = tid; u < 2048; u += NTHR) {
            int j  = u & 1;
            int hfx = (u >> 1) & 1;
            int i  = (u >> 2) & 7;
            int r  = (u >> 5) & 7;
            int wx = (u >> 8) & 7;
            int m   = (wx * 2 + hfx) * 16 + 2 * i + j;
            int row = (r >> 1) * 256 + j0 + (r & 1);
            W0u[u] = pack2(Whh0[row * 256 + m]);
            W1u[u] = pack2(Wih1[row * 256 + m]);
            WHu[u] = pack2(Whh1[row * 256 + m]);
        }
        if (tid < 8) {
            int row = (tid >> 1) * 256 + j0 + (tid & 1);
            b0s[tid] = bih0[row] + bhh0[row];
            b1s[tid] = bih1[row] + bhh1[row];
            for (int k = 0; k < 4; k++) wih0[tid * 4 + k] = Wih0[row * 4 + k];
        }
        if (tid < 128) { c0s[tid] = 0.0f; c1s[tid] = 0.0f; }
        if (tid < 256) { wout[tid] = Wout[tid]; wout[256 + tid] = Wout[256 + tid]; }
        if (tid < 2) bo2[tid] = bout[tid];
    }
    grid_barrier(tid, ls);   // round 1

    // ======== persistent 2-layer LSTM (layer1 two steps behind layer0) ========
    const int w    = tid >> 5;
    const int lane = tid & 31;
    const int hf   = lane >> 4;          // half-warp
    const int g    = lane & 15;          // bp-group -> batches 4g..4g+3
    const int q    = w * 2 + hf;         // 16 m-chunks of 16
    const int wb   = w * 128 + hf;       // ull2 weight index base: + r*16 + i*2
    const int hoff = q * 16 * 64 + 4 * g;

    ulonglong2 h0k[8];                   // kept: h0(p-2)[q-chunk m 0..7]
    #pragma unroll
    for (int k = 0; k < 8; k++) h0k[k] = make_ulonglong2(0ull, 0ull);

    for (int p = 0; p <= T_STEPS + 1; p++) {
        const float* H0m1 = &g_h0[(p + 2) % 3][0][0] + hoff;  // h0(p-1)
        const float* H0m2 = &g_h0[(p + 1) % 3][0][0] + hoff;  // h0(p-2)
        const float* H1o  = &g_h1[p][0][0] + hoff;            // h1(p-3) (slot (p-3)+3)
        if (p < T_STEPS) yw[tid] = g_yT[p + (tid >> 6)][tid & 63];

        ull a0lo[8], a0hi[8], a1lo[8], a1hi[8];
        #pragma unroll
        for (int r = 0; r < 8; r++) { a0lo[r]=0; a0hi[r]=0; a1lo[r]=0; a1hi[r]=0; }

        ulonglong2 h0o2[8], h1a[8], h1b[8], h0n1[8], h0n2[8];

        // (1) issue loads for the parts not kept in regs
        #pragma unroll
        for (int k = 0; k < 8; k++) h0o2[k] = ldcg2(H0m2 + (8 + k) * 64);
        #pragma unroll
        for (int k = 0; k < 8; k++) h1a[k]  = ldcg2(H1o + k * 64);

        // (2) layer1-ih half1 from KEPT regs -> starts with zero latency
        FMA8(W1v, 0, h0k, a1lo, a1hi);

        // (3) issue h1 second half
        #pragma unroll
        for (int k = 0; k < 8; k++) h1b[k] = ldcg2(H1o + (8 + k) * 64);

        // (4) layer1-ih half2 from streamed h0(p-2)[8..15]
        FMA8(W1v, 4, h0o2, a1lo, a1hi);

        // (5) issue layer0's h0(p-1) first half (kept for next phase)
        #pragma unroll
        for (int k = 0; k < 8; k++) h0n1[k] = ldcg2(H0m1 + k * 64);

        // (6) layer1-hh half1
        FMA8(WHv, 0, h1a, a1lo, a1hi);

        // (7) issue h0(p-1) second half
        #pragma unroll
        for (int k = 0; k < 8; k++) h0n2[k] = ldcg2(H0m1 + (8 + k) * 64);

        // (8) layer1-hh half2
        FMA8(WHv, 4, h1b, a1lo, a1hi);

        // (9,10) layer0 from h0(p-1)
        FMA8(W0v, 0, h0n1, a0lo, a0hi);
        FMA8(W0v, 4, h0n2, a0lo, a0hi);

        // keep h0(p-1)[0..7] for next phase's layer1-ih
        #pragma unroll
        for (int k = 0; k < 8; k++) h0k[k] = h0n1[k];

        #pragma unroll
        for (int r = 0; r < 8; r++) {
            P0v[(q * 8 + r) * 16 + g] = make_ulonglong2(a0lo[r], a0hi[r]);
            P1v[(q * 8 + r) * 16 + g] = make_ulonglong2(a1lo[r], a1hi[r]);
        }
        __syncthreads();

        // ---- reduce 16 partials, cell update, publish h ----
        {
            const int lb    = tid & 63;
            const int lj    = (tid >> 6) & 1;
            const int half2 = tid >> 7;     // 0: layer0 (step p), 1: layer1 (step p-2)
            const bool act  = half2 ? (p >= 2) : (p < T_STEPS);
            if (act) {
                const float* P = (const float*)(half2 ? P1v : P0v);
                float gg[4];
                #pragma unroll
                for (int gt = 0; gt < 4; gt++) {
                    int r = gt * 2 + lj;
                    float s = 0.0f;
                    #pragma unroll
                    for (int qq = 0; qq < 16; qq++)
                        s += P[(qq * 8 + r) * 64 + lb];
                    gg[gt] = s;
                }
                if (half2 == 0) {
                    #pragma unroll
                    for (int gt = 0; gt < 4; gt++) {
                        int r = gt * 2 + lj;
                        float s = gg[gt] + b0s[r];
                        #pragma unroll
                        for (int k = 0; k < 4; k++)
                            s = fmaf(yw[k * 64 + lb], wih0[r * 4 + k], s);
                        gg[gt] = s;
                    }
                } else {
                    #pragma unroll
                    for (int gt = 0; gt < 4; gt++)
                        gg[gt] += b1s[gt * 2 + lj];
                }
                float* cs = half2 ? c1s : c0s;
                float c = cs[lj * 64 + lb];
                c = sigf(gg[1]) * c + sigf(gg[0]) * tanh_f(gg[2]);
                cs[lj * 64 + lb] = c;
                float h = sigf(gg[3]) * tanh_f(c);
                int j = j0 + lj;
                if (half2 == 0) g_h0[p % 3][j][lb] = h;     // h0(p)
                else            g_h1[p + 1][j][lb] = h;     // h1(p-2) at slot (p-2)+3
            }
        }
        grid_barrier(tid, ls);   // rounds 2..4099
    }
    grid_barrier(tid, ls);       // round 4100 (keep total even -> sense returns to 0)

    // ======== output projection: out[b][t][k] = h1(t).Wout[k] + bout[k] ========
    {
        const int b  = tid & 63;
        const int tt = tid >> 6;    // 0..3
        #pragma unroll
        for (int u = 0; u < 8; u++) {
            int t = bid * 32 + tt * 8 + u;
            const float* h = &g_h1[t + 3][0][0];
            float s0 = bo2[0], s1 = bo2[1];
            #pragma unroll 8
            for (int m = 0; m < 256; m++) {
                float v = h[m * 64 + b];
                s0 = fmaf(v, wout[m],       s0);
                s1 = fmaf(v, wout[256 + m], s1);
            }
            out[b * (T_STEPS * 2) + t * 2 + 0] = s0;
            out[b * (T_STEPS * 2) + t * 2 + 1] = s1;
        }
    }
}

// ---------------- launcher: ONE kernel ----------------
extern "C" void kernel_launch(void* const* d_in, const int* in_sizes, int n_in,
                              void* d_out, int out_size)
{
    (void)in_sizes; (void)n_in; (void)out_size;
    cudaFuncSetAttribute(lstm_all, cudaFuncAttributeMaxDynamicSharedMemorySize, SMEM_BYTES);
    lstm_all<<<NCTA, NTHR, SMEM_BYTES>>>(
        (const float*)d_in[0],
        (const float*)d_in[1], (const float*)d_in[2],
        (const float*)d_in[3], (const float*)d_in[4],
        (const float*)d_in[5], (const float*)d_in[6],
        (const float*)d_in[7], (const float*)d_in[8],
        (const float*)d_in[9], (const float*)d_in[10],
        (float*)d_out);
}